// round 11
// baseline (speedup 1.0000x reference)
#include <cuda_runtime.h>
#include <cuda_fp16.h>

#define NN 50000
#define EE 800000
#define GG 256
#define FMAX 128
#define NB_SCAN 49      // ceil(50000/1024)
#define NE4_BLOCKS 782  // ceil(EE/4/256)
#define MM_BLOCKS 592

// stat offsets: L1=0(16) L2=128(32) L3=256(64) L4=384(64) L5=512(128)
__device__ unsigned long long g_pack[NN];   // count<<42 | weightsum_fx32
__device__ float  g_dis[NN];
__device__ int    g_rowptr[NN + 1];
__device__ int    g_blocksum[64];
__device__ int    g_gcnt[GG];
__device__ int    g_bar1;
__device__ int2   g_edge[EE];          // {src, float_bits(norm_w)}
__device__ float  g_bufA[NN * 64];     // h1(16) / h3(64)
__device__ float  g_bufB[NN * 64];     // h2(32) / c4(64)
__device__ float  g_m[NN * 16];        // L1 matmul out
__device__ double g_sum[640];
__device__ double g_sq[640];
__device__ float  g_pooled[GG * FMAX]; // raw per-graph sums of c5

// ---------------- preprocessing ----------------
__global__ void init_kernel() {
    int i = blockIdx.x * blockDim.x + threadIdx.x;
    if (i < NN) g_pack[i] = 0ULL;
    if (i < GG * FMAX) g_pooled[i] = 0.0f;
    if (i < 640) { g_sum[i] = 0.0; g_sq[i] = 0.0; }
    if (i < GG) g_gcnt[i] = 0;
    if (i == 0) g_bar1 = 0;
}

// fused: blocks [0,NE4) count 4 edges/thread; blocks [NE4,NE4+MM) do m = x @ W1
__global__ __launch_bounds__(256)
void count_mm_kernel(const int* __restrict__ ei, const float* __restrict__ ew,
                     const float* __restrict__ x, const float* __restrict__ W1,
                     float* __restrict__ out) {
    if (blockIdx.x < NE4_BLOCKS) {
        int base = (blockIdx.x * 256 + threadIdx.x) * 4;
        if (base < EE) {   // EE % 4 == 0 so base<EE => base+3<EE
            int4   c4 = *(const int4*)(ei + EE + base);
            float4 w4 = *(const float4*)(ew + base);
            atomicAdd(&g_pack[c4.x], (1ULL << 42) | (unsigned long long)(w4.x * 4294967296.0f));
            atomicAdd(&g_pack[c4.y], (1ULL << 42) | (unsigned long long)(w4.y * 4294967296.0f));
            atomicAdd(&g_pack[c4.z], (1ULL << 42) | (unsigned long long)(w4.z * 4294967296.0f));
            atomicAdd(&g_pack[c4.w], (1ULL << 42) | (unsigned long long)(w4.w * 4294967296.0f));
        }
        return;
    }
    int lane = threadIdx.x & 31;
    int bid = blockIdx.x - NE4_BLOCKS;
    int gwarp = (bid * 256 + threadIdx.x) >> 5;
    const int nwarps = MM_BLOCKS * 8;
    float w[4][16];
    #pragma unroll
    for (int j = 0; j < 4; j++) {
        #pragma unroll
        for (int c = 0; c < 16; c += 4) {
            float4 v = __ldg((const float4*)(W1 + (lane * 4 + j) * 16 + c));
            w[j][c] = v.x; w[j][c+1] = v.y; w[j][c+2] = v.z; w[j][c+3] = v.w;
        }
    }
    for (int node = gwarp; node < NN; node += nwarps) {
        float4 xv = __ldg((const float4*)(x + node * 128 + lane * 4));
        float acc[16];
        #pragma unroll
        for (int c = 0; c < 16; c++)
            acc[c] = xv.x * w[0][c] + xv.y * w[1][c] + xv.z * w[2][c] + xv.w * w[3][c];
        #pragma unroll
        for (int r = 0; r < 4; r++) {
            const int off  = 16 >> r;
            const int nrem = 8 >> r;
            bool hi = (lane & off) != 0;
            #pragma unroll
            for (int j = 0; j < nrem; j++) {
                float send = hi ? acc[j] : acc[j + nrem];
                float keep = hi ? acc[j + nrem] : acc[j];
                acc[j] = keep + __shfl_xor_sync(0xffffffffu, send, off);
            }
        }
        acc[0] += __shfl_xor_sync(0xffffffffu, acc[0], 1);
        if (!(lane & 1)) out[node * 16 + (lane >> 1)] = acc[0];
    }
}

// merged scan: dis + gcnt + local scan -> [gbar] -> global rowptr starts
__global__ __launch_bounds__(1024)
void scan_kernel(const int* __restrict__ batch) {
    __shared__ int s[1024];
    __shared__ int soff;
    int t = threadIdx.x;
    int i = blockIdx.x * 1024 + t;
    unsigned long long p = (i < NN) ? g_pack[i] : 0ULL;
    int v = (int)(p >> 42);
    s[t] = v;
    if (i < NN) {
        double wfx = (double)(p & ((1ULL << 42) - 1ULL)) * 2.3283064365386963e-10;
        g_dis[i] = rsqrtf((float)(1.0 + wfx));
        atomicAdd(&g_gcnt[batch[i]], 1);
    }
    __syncthreads();
    #pragma unroll
    for (int off = 1; off < 1024; off <<= 1) {
        int x = (t >= off) ? s[t - off] : 0;
        __syncthreads();
        s[t] += x;
        __syncthreads();
    }
    int local_excl = s[t] - v;
    if (t == 1023) g_blocksum[blockIdx.x] = s[1023];
    __syncthreads();
    if (t == 0) {
        __threadfence();
        atomicAdd(&g_bar1, 1);
        while (atomicAdd(&g_bar1, 0) < NB_SCAN) __nanosleep(32);
        int off = 0;
        for (int b = 0; b < blockIdx.x; b++) off += g_blocksum[b];
        soff = off;
    }
    __syncthreads();
    if (i < NN) g_rowptr[i] = soff + local_excl;
}

// scatter 4 edges/thread; rowptr[c] doubles as fill cursor
__global__ __launch_bounds__(256)
void scatter_kernel(const int* __restrict__ ei, const float* __restrict__ ew) {
    int base = (blockIdx.x * 256 + threadIdx.x) * 4;
    if (base >= EE) return;
    int4   r4 = *(const int4*)(ei + base);
    int4   c4 = *(const int4*)(ei + EE + base);
    float4 w4 = *(const float4*)(ew + base);
    float dr0 = __ldg(&g_dis[r4.x]), dc0 = __ldg(&g_dis[c4.x]);
    float dr1 = __ldg(&g_dis[r4.y]), dc1 = __ldg(&g_dis[c4.y]);
    float dr2 = __ldg(&g_dis[r4.z]), dc2 = __ldg(&g_dis[c4.z]);
    float dr3 = __ldg(&g_dis[r4.w]), dc3 = __ldg(&g_dis[c4.w]);
    int p0 = atomicAdd(&g_rowptr[c4.x], 1);
    int p1 = atomicAdd(&g_rowptr[c4.y], 1);
    int p2 = atomicAdd(&g_rowptr[c4.z], 1);
    int p3 = atomicAdd(&g_rowptr[c4.w], 1);
    g_edge[p0] = make_int2(r4.x, __float_as_int(dr0 * w4.x * dc0));
    g_edge[p1] = make_int2(r4.y, __float_as_int(dr1 * w4.y * dc1));
    g_edge[p2] = make_int2(r4.z, __float_as_int(dr2 * w4.z * dc2));
    g_edge[p3] = make_int2(r4.w, __float_as_int(dr3 * w4.w * dc3));
}

// ---------------- L1 aggregate + bias + relu + stats ----------------
template <int DOUT>
__global__ __launch_bounds__(256)
void aggregate_post_kernel(const float* __restrict__ m, const float* __restrict__ b,
                           float* __restrict__ out, int stat_off) {
    constexpr int NT  = DOUT / 4;
    constexpr int NPB = 256 / NT;
    __shared__ float s_sum[DOUT], s_sq[DOUT];
    int tid = threadIdx.x;
    for (int i = tid; i < DOUT; i += 256) { s_sum[i] = 0.f; s_sq[i] = 0.f; }
    __syncthreads();
    int lane = tid % NT;
    int node = blockIdx.x * NPB + tid / NT;
    const float4* m4 = (const float4*)m;
    if (node < NN) {
        float dn = g_dis[node];
        float sn = dn * dn;
        float a0 = b[lane*4+0], a1 = b[lane*4+1], a2 = b[lane*4+2], a3 = b[lane*4+3];
        float4 mv = __ldg(m4 + node * NT + lane);
        a0 += sn * mv.x; a1 += sn * mv.y; a2 += sn * mv.z; a3 += sn * mv.w;
        int e0 = node ? g_rowptr[node - 1] : 0;
        int e1 = g_rowptr[node];
        int e = e0;
        for (; e + 4 <= e1; e += 4) {
            int2 eA = __ldg(&g_edge[e]);
            int2 eB = __ldg(&g_edge[e + 1]);
            int2 eC = __ldg(&g_edge[e + 2]);
            int2 eD = __ldg(&g_edge[e + 3]);
            float wA = __int_as_float(eA.y), wB = __int_as_float(eB.y);
            float wC = __int_as_float(eC.y), wD = __int_as_float(eD.y);
            float4 vA = __ldg(m4 + eA.x * NT + lane);
            float4 vB = __ldg(m4 + eB.x * NT + lane);
            float4 vC = __ldg(m4 + eC.x * NT + lane);
            float4 vD = __ldg(m4 + eD.x * NT + lane);
            a0 += wA*vA.x + wB*vB.x + wC*vC.x + wD*vD.x;
            a1 += wA*vA.y + wB*vB.y + wC*vC.y + wD*vD.y;
            a2 += wA*vA.z + wB*vB.z + wC*vC.z + wD*vD.z;
            a3 += wA*vA.w + wB*vB.w + wC*vC.w + wD*vD.w;
        }
        for (; e < e1; e++) {
            int2 ev = __ldg(&g_edge[e]);
            float w = __int_as_float(ev.y);
            float4 v = __ldg(m4 + ev.x * NT + lane);
            a0 += w * v.x; a1 += w * v.y; a2 += w * v.z; a3 += w * v.w;
        }
        a0 = fmaxf(a0, 0.f); a1 = fmaxf(a1, 0.f);
        a2 = fmaxf(a2, 0.f); a3 = fmaxf(a3, 0.f);
        ((float4*)out)[node * NT + lane] = make_float4(a0, a1, a2, a3);
        atomicAdd(&s_sum[lane*4+0], a0); atomicAdd(&s_sq[lane*4+0], a0*a0);
        atomicAdd(&s_sum[lane*4+1], a1); atomicAdd(&s_sq[lane*4+1], a1*a1);
        atomicAdd(&s_sum[lane*4+2], a2); atomicAdd(&s_sq[lane*4+2], a2*a2);
        atomicAdd(&s_sum[lane*4+3], a3); atomicAdd(&s_sq[lane*4+3], a3*a3);
    }
    __syncthreads();
    for (int i = tid; i < DOUT; i += 256) {
        atomicAdd(&g_sum[stat_off + i], (double)s_sum[i]);
        atomicAdd(&g_sq[stat_off + i],  (double)s_sq[i]);
    }
}

// ---------------- fused: gather(BN-in) -> matmul -> bias(+relu) + stats [+pool] ----------------
template <int DIN, int DOUT, int MODE_IN, bool RELU_OUT, int TILE, int TPN, int OUT_MODE>
__global__ __launch_bounds__(512)
void fused_layer_kernel(const float* __restrict__ h, const float* __restrict__ W,
                        const float* __restrict__ bias, float* __restrict__ out,
                        const float* __restrict__ gamma, const float* __restrict__ beta,
                        const int* __restrict__ batch,
                        int stat_in, int stat_out) {
    static_assert(TILE * TPN == 512, "gather uses all threads");
    constexpr int CG  = DOUT / 4;
    constexpr int RG  = 512 / CG;
    constexpr int RPT = TILE / RG;
    constexpr int F4  = DIN / 4 / TPN;
    extern __shared__ float smem[];
    float* sW = smem;
    float* sH = smem + DIN * DOUT;
    __shared__ float sS[DIN], sF[DIN];
    __shared__ float s_sum[DOUT], s_sq[DOUT];
    int t = threadIdx.x;
    if (t < DIN) {
        double mu  = g_sum[stat_in + t] / (double)NN;
        double var = g_sq[stat_in + t] / (double)NN - mu * mu;
        if (var < 0.0) var = 0.0;
        double sc = (double)gamma[t] * rsqrt(var + 1e-5);
        sS[t] = (float)sc;
        sF[t] = (float)((double)beta[t] - mu * sc);
    }
    for (int i = t; i < DOUT; i += 512) { s_sum[i] = 0.f; s_sq[i] = 0.f; }
    for (int i = t; i < DIN * DOUT / 4; i += 512)
        ((float4*)sW)[i] = ((const float4*)W)[i];
    __syncthreads();

    int node0 = blockIdx.x * TILE;
    // ---- gather phase ----
    {
        int local = t / TPN;
        int sub   = t % TPN;
        int base  = sub * F4;
        int node  = node0 + local;
        float a[F4][4];
        #pragma unroll
        for (int j = 0; j < F4; j++) { a[j][0]=0.f; a[j][1]=0.f; a[j][2]=0.f; a[j][3]=0.f; }
        if (node < NN) {
            const float4* h4 = (const float4*)h;
            float rs[F4][4], rf[F4][4];
            #pragma unroll
            for (int j = 0; j < F4; j++) {
                int c = (base + j) * 4;
                rs[j][0]=sS[c]; rs[j][1]=sS[c+1]; rs[j][2]=sS[c+2]; rs[j][3]=sS[c+3];
                rf[j][0]=sF[c]; rf[j][1]=sF[c+1]; rf[j][2]=sF[c+2]; rf[j][3]=sF[c+3];
            }
            auto accv = [&](const float4* v, float w) {
                #pragma unroll
                for (int j = 0; j < F4; j++) {
                    if (MODE_IN == 1) {
                        a[j][0] += w * fmaxf(rs[j][0]*v[j].x + rf[j][0], 0.f);
                        a[j][1] += w * fmaxf(rs[j][1]*v[j].y + rf[j][1], 0.f);
                        a[j][2] += w * fmaxf(rs[j][2]*v[j].z + rf[j][2], 0.f);
                        a[j][3] += w * fmaxf(rs[j][3]*v[j].w + rf[j][3], 0.f);
                    } else {
                        a[j][0] += w*v[j].x; a[j][1] += w*v[j].y;
                        a[j][2] += w*v[j].z; a[j][3] += w*v[j].w;
                    }
                }
            };
            float dn = g_dis[node];
            float sn = dn * dn;
            float wsum = sn;
            {
                float4 v[F4];
                #pragma unroll
                for (int j = 0; j < F4; j++) v[j] = __ldg(h4 + node * (DIN/4) + base + j);
                accv(v, sn);
            }
            int e0 = node ? g_rowptr[node - 1] : 0;
            int e1 = g_rowptr[node];
            int e = e0;
            if constexpr (F4 == 1) {
                for (; e + 4 <= e1; e += 4) {
                    int2 eA = __ldg(&g_edge[e]);
                    int2 eB = __ldg(&g_edge[e + 1]);
                    int2 eC = __ldg(&g_edge[e + 2]);
                    int2 eD = __ldg(&g_edge[e + 3]);
                    float wA = __int_as_float(eA.y), wB = __int_as_float(eB.y);
                    float wC = __int_as_float(eC.y), wD = __int_as_float(eD.y);
                    float4 vA[1], vB[1], vC[1], vD[1];
                    vA[0] = __ldg(h4 + eA.x * (DIN/4) + base);
                    vB[0] = __ldg(h4 + eB.x * (DIN/4) + base);
                    vC[0] = __ldg(h4 + eC.x * (DIN/4) + base);
                    vD[0] = __ldg(h4 + eD.x * (DIN/4) + base);
                    accv(vA, wA); accv(vB, wB); accv(vC, wC); accv(vD, wD);
                    wsum += wA + wB + wC + wD;
                }
            }
            for (; e + 2 <= e1; e += 2) {
                int2 eA = __ldg(&g_edge[e]);
                int2 eB = __ldg(&g_edge[e + 1]);
                float wA = __int_as_float(eA.y), wB = __int_as_float(eB.y);
                float4 vA[F4], vB[F4];
                #pragma unroll
                for (int j = 0; j < F4; j++) vA[j] = __ldg(h4 + eA.x * (DIN/4) + base + j);
                #pragma unroll
                for (int j = 0; j < F4; j++) vB[j] = __ldg(h4 + eB.x * (DIN/4) + base + j);
                accv(vA, wA); accv(vB, wB);
                wsum += wA + wB;
            }
            if (e < e1) {
                int2 ev = __ldg(&g_edge[e]);
                float w = __int_as_float(ev.y);
                float4 v[F4];
                #pragma unroll
                for (int j = 0; j < F4; j++) v[j] = __ldg(h4 + ev.x * (DIN/4) + base + j);
                accv(v, w);
                wsum += w;
            }
            if (MODE_IN == 0) {
                #pragma unroll
                for (int j = 0; j < F4; j++) {
                    a[j][0] = rs[j][0]*a[j][0] + rf[j][0]*wsum;
                    a[j][1] = rs[j][1]*a[j][1] + rf[j][1]*wsum;
                    a[j][2] = rs[j][2]*a[j][2] + rf[j][2]*wsum;
                    a[j][3] = rs[j][3]*a[j][3] + rf[j][3]*wsum;
                }
            }
        }
        #pragma unroll
        for (int j = 0; j < F4; j++)
            ((float4*)sH)[local * (DIN / 4) + base + j] =
                make_float4(a[j][0], a[j][1], a[j][2], a[j][3]);
    }
    __syncthreads();

    // ---- matmul phase ----
    int cg = t % CG, rg = t / CG;
    float acc[RPT][4];
    #pragma unroll
    for (int r = 0; r < RPT; r++) { acc[r][0]=0.f; acc[r][1]=0.f; acc[r][2]=0.f; acc[r][3]=0.f; }
    const float* sHr = sH + rg * RPT * DIN;
    #pragma unroll 8
    for (int k = 0; k < DIN; k++) {
        float4 wv = *(const float4*)(sW + k * DOUT + cg * 4);
        #pragma unroll
        for (int r = 0; r < RPT; r++) {
            float hv = sHr[r * DIN + k];
            acc[r][0] += hv * wv.x; acc[r][1] += hv * wv.y;
            acc[r][2] += hv * wv.z; acc[r][3] += hv * wv.w;
        }
    }
    float b0 = bias[cg*4+0], b1 = bias[cg*4+1], b2 = bias[cg*4+2], b3 = bias[cg*4+3];
    float ls0=0.f, ls1=0.f, ls2=0.f, ls3=0.f, lq0=0.f, lq1=0.f, lq2=0.f, lq3=0.f;
    float p0=0.f, p1=0.f, p2=0.f, p3=0.f;
    int curg = -1;
    #pragma unroll
    for (int r = 0; r < RPT; r++) {
        int node = node0 + rg * RPT + r;
        if (node < NN) {
            float v0 = acc[r][0] + b0, v1 = acc[r][1] + b1;
            float v2 = acc[r][2] + b2, v3 = acc[r][3] + b3;
            if (RELU_OUT) {
                v0 = fmaxf(v0, 0.f); v1 = fmaxf(v1, 0.f);
                v2 = fmaxf(v2, 0.f); v3 = fmaxf(v3, 0.f);
            }
            if (OUT_MODE == 0) {
                ((float4*)out)[node * CG + cg] = make_float4(v0, v1, v2, v3);
            } else {
                int bg = batch[node];
                if (bg != curg) {
                    if (curg >= 0) {
                        atomicAdd(&g_pooled[curg*FMAX + cg*4+0], p0);
                        atomicAdd(&g_pooled[curg*FMAX + cg*4+1], p1);
                        atomicAdd(&g_pooled[curg*FMAX + cg*4+2], p2);
                        atomicAdd(&g_pooled[curg*FMAX + cg*4+3], p3);
                    }
                    curg = bg; p0 = v0; p1 = v1; p2 = v2; p3 = v3;
                } else {
                    p0 += v0; p1 += v1; p2 += v2; p3 += v3;
                }
            }
            ls0 += v0; lq0 += v0*v0; ls1 += v1; lq1 += v1*v1;
            ls2 += v2; lq2 += v2*v2; ls3 += v3; lq3 += v3*v3;
        }
    }
    if (OUT_MODE == 2 && curg >= 0) {
        atomicAdd(&g_pooled[curg*FMAX + cg*4+0], p0);
        atomicAdd(&g_pooled[curg*FMAX + cg*4+1], p1);
        atomicAdd(&g_pooled[curg*FMAX + cg*4+2], p2);
        atomicAdd(&g_pooled[curg*FMAX + cg*4+3], p3);
    }
    atomicAdd(&s_sum[cg*4+0], ls0); atomicAdd(&s_sq[cg*4+0], lq0);
    atomicAdd(&s_sum[cg*4+1], ls1); atomicAdd(&s_sq[cg*4+1], lq1);
    atomicAdd(&s_sum[cg*4+2], ls2); atomicAdd(&s_sq[cg*4+2], lq2);
    atomicAdd(&s_sum[cg*4+3], ls3); atomicAdd(&s_sq[cg*4+3], lq3);
    __syncthreads();
    for (int i = t; i < DOUT; i += 512) {
        atomicAdd(&g_sum[stat_out + i], (double)s_sum[i]);
        atomicAdd(&g_sq[stat_out + i],  (double)s_sq[i]);
    }
}

// ---------------- final MLP (applies BN5 to raw pooled sums) ----------------
__global__ void mlp_kernel(const float* __restrict__ g5, const float* __restrict__ bt5,
                           const float* __restrict__ fc1_w, const float* __restrict__ fc1_b,
                           const float* __restrict__ fc2_w, const float* __restrict__ fc2_b,
                           float* __restrict__ out) {
    int g = blockIdx.x;
    int t = threadIdx.x;  // 64
    __shared__ float sp[FMAX];
    float cnt = (float)g_gcnt[g];
    for (int i = t; i < FMAX; i += 64) {
        double mu  = g_sum[512 + i] / (double)NN;
        double var = g_sq[512 + i] / (double)NN - mu * mu;
        if (var < 0.0) var = 0.0;
        double sc = (double)g5[i] * rsqrt(var + 1e-5);
        float f = (float)((double)bt5[i] - mu * sc);
        sp[i] = fmaxf((float)sc * g_pooled[g * FMAX + i] + f * cnt, 0.0f);
    }
    __syncthreads();
    float acc = fc1_b[t];
    #pragma unroll 4
    for (int k = 0; k < FMAX; k++) acc += sp[k] * fc1_w[k * 64 + t];
    acc = fmaxf(acc, 0.0f);
    float v = acc * fc2_w[t];
    #pragma unroll
    for (int off = 16; off > 0; off >>= 1) v += __shfl_down_sync(0xffffffffu, v, off);
    __shared__ float red[2];
    if ((t & 31) == 0) red[t >> 5] = v;
    __syncthreads();
    if (t == 0) out[g] = red[0] + red[1] + fc2_b[0];
}

// ---------------- launch ----------------
extern "C" void kernel_launch(void* const* d_in, const int* in_sizes, int n_in,
                              void* d_out, int out_size) {
    const float* x     = (const float*)d_in[0];
    const int*   ei    = (const int*)d_in[1];
    const float* ew    = (const float*)d_in[2];
    const int*   batch = (const int*)d_in[3];
    const float *W1 = (const float*)d_in[4],  *b1 = (const float*)d_in[5],
                *g1 = (const float*)d_in[6],  *bt1 = (const float*)d_in[7];
    const float *W2 = (const float*)d_in[8],  *b2 = (const float*)d_in[9],
                *g2 = (const float*)d_in[10], *bt2 = (const float*)d_in[11];
    const float *W3 = (const float*)d_in[12], *b3 = (const float*)d_in[13],
                *g3 = (const float*)d_in[14], *bt3 = (const float*)d_in[15];
    const float *W4 = (const float*)d_in[16], *b4 = (const float*)d_in[17],
                *g4 = (const float*)d_in[18], *bt4 = (const float*)d_in[19];
    const float *W5 = (const float*)d_in[20], *b5 = (const float*)d_in[21],
                *g5 = (const float*)d_in[22], *bt5 = (const float*)d_in[23];
    const float* fc1_w = (const float*)d_in[24];
    const float* fc1_b = (const float*)d_in[25];
    const float* fc2_w = (const float*)d_in[26];
    const float* fc2_b = (const float*)d_in[27];
    float* out = (float*)d_out;

    float *bufA, *bufB, *bufM;
    cudaGetSymbolAddress((void**)&bufA, g_bufA);
    cudaGetSymbolAddress((void**)&bufB, g_bufB);
    cudaGetSymbolAddress((void**)&bufM, g_m);

    // opt-in smem for the L5 fused kernel
    cudaFuncSetAttribute(
        (const void*)fused_layer_kernel<64, 128, 1, false, 64, 8, 2>,
        cudaFuncAttributeMaxDynamicSharedMemorySize, 49152);

    const int TB = 256;
    init_kernel<<<(NN + TB - 1) / TB, TB>>>();
    count_mm_kernel<<<NE4_BLOCKS + MM_BLOCKS, 256>>>(ei, ew, x, W1, bufM);
    scan_kernel<<<NB_SCAN, 1024>>>(batch);
    scatter_kernel<<<NE4_BLOCKS, 256>>>(ei, ew);

    auto smem = [](int din, int dout, int tile) {
        return (din * dout + tile * din) * 4;
    };

    // L1 aggregate: m -> h1 (fp32) in bufA
    aggregate_post_kernel<16><<<(NN * 4 + 255) / 256, 256>>>(bufM, b1, bufA, 0);

    // L2 (16->32): h1 -> h2 in bufB
    fused_layer_kernel<16, 32, 0, true, 128, 4, 0>
        <<<(NN + 127) / 128, 512, smem(16, 32, 128)>>>(
        bufA, W2, b2, bufB, g1, bt1, nullptr, 0, 128);
    // L3 (32->64): h2 -> h3 in bufA
    fused_layer_kernel<32, 64, 0, true, 128, 4, 0>
        <<<(NN + 127) / 128, 512, smem(32, 64, 128)>>>(
        bufB, W3, b3, bufA, g2, bt2, nullptr, 128, 256);
    // L4 (64->64): h3 -> c4 in bufB (no relu-out)
    fused_layer_kernel<64, 64, 0, false, 64, 8, 0>
        <<<(NN + 63) / 64, 512, smem(64, 64, 64)>>>(
        bufA, W4, b4, bufB, g3, bt3, nullptr, 256, 384);
    // L5 (64->128): gather relu(bn(c4)); no output buffer — pool raw c5 per graph
    fused_layer_kernel<64, 128, 1, false, 64, 8, 2>
        <<<(NN + 63) / 64, 512, smem(64, 128, 64)>>>(
        bufB, W5, b5, nullptr, g4, bt4, batch, 384, 512);

    // MLP head (applies BN5 affine to pooled sums)
    mlp_kernel<<<GG, 64>>>(g5, bt5, fc1_w, fc1_b, fc2_w, fc2_b, out);
}

// round 12
// speedup vs baseline: 1.0773x; 1.0773x over previous
#include <cuda_runtime.h>
#include <cuda_fp16.h>

#define NN 50000
#define EE 800000
#define GG 256
#define FMAX 128
#define NB_SCAN 49      // ceil(50000/1024)
#define NC_BLOCKS 3125  // ceil(EE/256)
#define MM_BLOCKS 592

// stat offsets: L1=0(16) L2=128(32) L3=256(64) L4=384(64) L5=512(128)
// Self-cleaning invariant: every global below is returned to ZERO by the
// kernel that consumes it, so no init pass is needed across graph replays.
__device__ unsigned long long g_pack[NN];   // count<<42 | weightsum_fx32
__device__ float  g_dis[NN];
__device__ int    g_rowptr[NN + 1];
__device__ int    g_blocksum[64];
__device__ int    g_gcnt[GG];
__device__ int    g_bar1;
__device__ int2   g_edge[EE];          // {src, float_bits(norm_w)}
__device__ float  g_bufA[NN * 64];     // h1(16) / h3(64)
__device__ float  g_bufB[NN * 64];     // h2(32) / c4(64)
__device__ float  g_m[NN * 16];        // L1 matmul out
__device__ double g_sum[640];
__device__ double g_sq[640];
__device__ float  g_pooled[GG * FMAX]; // raw per-graph sums of c5

// fused: blocks [0,NC) count edges; blocks [NC,NC+MM) do m = x @ W1 (independent)
__global__ __launch_bounds__(256)
void count_mm_kernel(const int* __restrict__ ei, const float* __restrict__ ew,
                     const float* __restrict__ x, const float* __restrict__ W1,
                     float* __restrict__ out) {
    if (blockIdx.x < NC_BLOCKS) {
        int e = blockIdx.x * 256 + threadIdx.x;
        if (e < EE) {
            int c = ei[EE + e];
            unsigned long long p = (1ULL << 42) |
                (unsigned long long)(ew[e] * 4294967296.0f);
            atomicAdd(&g_pack[c], p);
        }
        return;
    }
    int lane = threadIdx.x & 31;
    int bid = blockIdx.x - NC_BLOCKS;
    int gwarp = (bid * 256 + threadIdx.x) >> 5;
    const int nwarps = MM_BLOCKS * 8;
    float w[4][16];
    #pragma unroll
    for (int j = 0; j < 4; j++) {
        #pragma unroll
        for (int c = 0; c < 16; c += 4) {
            float4 v = __ldg((const float4*)(W1 + (lane * 4 + j) * 16 + c));
            w[j][c] = v.x; w[j][c+1] = v.y; w[j][c+2] = v.z; w[j][c+3] = v.w;
        }
    }
    for (int node = gwarp; node < NN; node += nwarps) {
        float4 xv = __ldg((const float4*)(x + node * 128 + lane * 4));
        float acc[16];
        #pragma unroll
        for (int c = 0; c < 16; c++)
            acc[c] = xv.x * w[0][c] + xv.y * w[1][c] + xv.z * w[2][c] + xv.w * w[3][c];
        #pragma unroll
        for (int r = 0; r < 4; r++) {
            const int off  = 16 >> r;
            const int nrem = 8 >> r;
            bool hi = (lane & off) != 0;
            #pragma unroll
            for (int j = 0; j < nrem; j++) {
                float send = hi ? acc[j] : acc[j + nrem];
                float keep = hi ? acc[j + nrem] : acc[j];
                acc[j] = keep + __shfl_xor_sync(0xffffffffu, send, off);
            }
        }
        acc[0] += __shfl_xor_sync(0xffffffffu, acc[0], 1);
        if (!(lane & 1)) out[node * 16 + (lane >> 1)] = acc[0];
    }
}

// merged scan: dis + gcnt + local scan -> [gbar] -> global rowptr starts
// self-clean: zeroes g_pack after reading it.
__global__ __launch_bounds__(1024)
void scan_kernel(const int* __restrict__ batch) {
    __shared__ int s[1024];
    __shared__ int soff;
    int t = threadIdx.x;
    int i = blockIdx.x * 1024 + t;
    unsigned long long p = (i < NN) ? g_pack[i] : 0ULL;
    int v = (int)(p >> 42);
    s[t] = v;
    if (i < NN) {
        g_pack[i] = 0ULL;   // self-clean for next replay
        double wfx = (double)(p & ((1ULL << 42) - 1ULL)) * 2.3283064365386963e-10;
        g_dis[i] = rsqrtf((float)(1.0 + wfx));
        atomicAdd(&g_gcnt[batch[i]], 1);
    }
    __syncthreads();
    #pragma unroll
    for (int off = 1; off < 1024; off <<= 1) {
        int x = (t >= off) ? s[t - off] : 0;
        __syncthreads();
        s[t] += x;
        __syncthreads();
    }
    int local_excl = s[t] - v;
    if (t == 1023) g_blocksum[blockIdx.x] = s[1023];
    __syncthreads();
    if (t == 0) {
        __threadfence();
        atomicAdd(&g_bar1, 1);
        while (atomicAdd(&g_bar1, 0) < NB_SCAN) __nanosleep(32);
        int off = 0;
        for (int b = 0; b < blockIdx.x; b++) off += g_blocksum[b];
        soff = off;
    }
    __syncthreads();
    if (i < NN) g_rowptr[i] = soff + local_excl;
}

// scatter; rowptr[c] doubles as fill cursor. self-clean: resets g_bar1.
__global__ void scatter_kernel(const int* __restrict__ ei, const float* __restrict__ ew) {
    if (blockIdx.x == 0 && threadIdx.x == 0) g_bar1 = 0;  // scan fully done
    int e = blockIdx.x * blockDim.x + threadIdx.x;
    if (e < EE) {
        int r = ei[e];
        int c = ei[EE + e];
        int pos = atomicAdd(&g_rowptr[c], 1);
        float w = g_dis[r] * ew[e] * g_dis[c];
        g_edge[pos] = make_int2(r, __float_as_int(w));
    }
}

// ---------------- L1 aggregate + bias + relu + stats ----------------
// self-clean duty: block 0 zeroes stats region 512 (read by last replay's mlp,
// written later this replay by L5).
template <int DOUT>
__global__ __launch_bounds__(256)
void aggregate_post_kernel(const float* __restrict__ m, const float* __restrict__ b,
                           float* __restrict__ out, int stat_off) {
    constexpr int NT  = DOUT / 4;
    constexpr int NPB = 256 / NT;
    __shared__ float s_sum[DOUT], s_sq[DOUT];
    int tid = threadIdx.x;
    if (blockIdx.x == 0) {
        for (int i = tid; i < 128; i += 256) { g_sum[512 + i] = 0.0; g_sq[512 + i] = 0.0; }
    }
    for (int i = tid; i < DOUT; i += 256) { s_sum[i] = 0.f; s_sq[i] = 0.f; }
    __syncthreads();
    int lane = tid % NT;
    int node = blockIdx.x * NPB + tid / NT;
    const float4* m4 = (const float4*)m;
    if (node < NN) {
        float dn = g_dis[node];
        float sn = dn * dn;
        float a0 = b[lane*4+0], a1 = b[lane*4+1], a2 = b[lane*4+2], a3 = b[lane*4+3];
        float4 mv = __ldg(m4 + node * NT + lane);
        a0 += sn * mv.x; a1 += sn * mv.y; a2 += sn * mv.z; a3 += sn * mv.w;
        int e0 = node ? g_rowptr[node - 1] : 0;
        int e1 = g_rowptr[node];
        int e = e0;
        for (; e + 2 <= e1; e += 2) {
            int2 eA = __ldg(&g_edge[e]);
            int2 eB = __ldg(&g_edge[e + 1]);
            float wA = __int_as_float(eA.y), wB = __int_as_float(eB.y);
            float4 vA = __ldg(m4 + eA.x * NT + lane);
            float4 vB = __ldg(m4 + eB.x * NT + lane);
            a0 += wA * vA.x + wB * vB.x; a1 += wA * vA.y + wB * vB.y;
            a2 += wA * vA.z + wB * vB.z; a3 += wA * vA.w + wB * vB.w;
        }
        if (e < e1) {
            int2 ev = __ldg(&g_edge[e]);
            float w = __int_as_float(ev.y);
            float4 v = __ldg(m4 + ev.x * NT + lane);
            a0 += w * v.x; a1 += w * v.y; a2 += w * v.z; a3 += w * v.w;
        }
        a0 = fmaxf(a0, 0.f); a1 = fmaxf(a1, 0.f);
        a2 = fmaxf(a2, 0.f); a3 = fmaxf(a3, 0.f);
        ((float4*)out)[node * NT + lane] = make_float4(a0, a1, a2, a3);
        atomicAdd(&s_sum[lane*4+0], a0); atomicAdd(&s_sq[lane*4+0], a0*a0);
        atomicAdd(&s_sum[lane*4+1], a1); atomicAdd(&s_sq[lane*4+1], a1*a1);
        atomicAdd(&s_sum[lane*4+2], a2); atomicAdd(&s_sq[lane*4+2], a2*a2);
        atomicAdd(&s_sum[lane*4+3], a3); atomicAdd(&s_sq[lane*4+3], a3*a3);
    }
    __syncthreads();
    for (int i = tid; i < DOUT; i += 256) {
        atomicAdd(&g_sum[stat_off + i], (double)s_sum[i]);
        atomicAdd(&g_sq[stat_off + i],  (double)s_sq[i]);
    }
}

// ---------------- fused: gather(BN-in) -> matmul -> bias(+relu) + stats [+pool] ----------------
// MODE_IN 0: bn folded out of loop; 1: relu(bn) per element.
// OUT_MODE 0: write float4 rows; 2: no output buffer, pool raw values per graph.
// STAT_ZERO >= 0: block 0 zeroes stats region [STAT_ZERO, STAT_ZERO+128) —
//   the region whose last reader was the PREVIOUS fused layer (self-clean).
template <int DIN, int DOUT, int MODE_IN, bool RELU_OUT, int TILE, int TPN, int OUT_MODE,
          int STAT_ZERO>
__global__ __launch_bounds__(512)
void fused_layer_kernel(const float* __restrict__ h, const float* __restrict__ W,
                        const float* __restrict__ bias, float* __restrict__ out,
                        const float* __restrict__ gamma, const float* __restrict__ beta,
                        const int* __restrict__ batch,
                        int stat_in, int stat_out) {
    static_assert(TILE * TPN == 512, "gather uses all threads");
    constexpr int CG  = DOUT / 4;
    constexpr int RG  = 512 / CG;
    constexpr int RPT = TILE / RG;
    constexpr int F4  = DIN / 4 / TPN;
    extern __shared__ float smem[];
    float* sW = smem;
    float* sH = smem + DIN * DOUT;
    __shared__ float sS[DIN], sF[DIN];
    __shared__ float s_sum[DOUT], s_sq[DOUT];
    int t = threadIdx.x;
    if (STAT_ZERO >= 0 && blockIdx.x == 0) {
        for (int i = t; i < 128; i += 512) {
            g_sum[STAT_ZERO + i] = 0.0; g_sq[STAT_ZERO + i] = 0.0;
        }
    }
    if (t < DIN) {
        double mu  = g_sum[stat_in + t] / (double)NN;
        double var = g_sq[stat_in + t] / (double)NN - mu * mu;
        if (var < 0.0) var = 0.0;
        double sc = (double)gamma[t] * rsqrt(var + 1e-5);
        sS[t] = (float)sc;
        sF[t] = (float)((double)beta[t] - mu * sc);
    }
    for (int i = t; i < DOUT; i += 512) { s_sum[i] = 0.f; s_sq[i] = 0.f; }
    for (int i = t; i < DIN * DOUT / 4; i += 512)
        ((float4*)sW)[i] = ((const float4*)W)[i];
    __syncthreads();

    int node0 = blockIdx.x * TILE;
    // ---- gather phase ----
    {
        int local = t / TPN;
        int sub   = t % TPN;
        int base  = sub * F4;
        int node  = node0 + local;
        float a[F4][4];
        #pragma unroll
        for (int j = 0; j < F4; j++) { a[j][0]=0.f; a[j][1]=0.f; a[j][2]=0.f; a[j][3]=0.f; }
        if (node < NN) {
            const float4* h4 = (const float4*)h;
            float rs[F4][4], rf[F4][4];
            #pragma unroll
            for (int j = 0; j < F4; j++) {
                int c = (base + j) * 4;
                rs[j][0]=sS[c]; rs[j][1]=sS[c+1]; rs[j][2]=sS[c+2]; rs[j][3]=sS[c+3];
                rf[j][0]=sF[c]; rf[j][1]=sF[c+1]; rf[j][2]=sF[c+2]; rf[j][3]=sF[c+3];
            }
            auto accv = [&](const float4* v, float w) {
                #pragma unroll
                for (int j = 0; j < F4; j++) {
                    if (MODE_IN == 1) {
                        a[j][0] += w * fmaxf(rs[j][0]*v[j].x + rf[j][0], 0.f);
                        a[j][1] += w * fmaxf(rs[j][1]*v[j].y + rf[j][1], 0.f);
                        a[j][2] += w * fmaxf(rs[j][2]*v[j].z + rf[j][2], 0.f);
                        a[j][3] += w * fmaxf(rs[j][3]*v[j].w + rf[j][3], 0.f);
                    } else {
                        a[j][0] += w*v[j].x; a[j][1] += w*v[j].y;
                        a[j][2] += w*v[j].z; a[j][3] += w*v[j].w;
                    }
                }
            };
            float dn = g_dis[node];
            float sn = dn * dn;
            float wsum = sn;
            {
                float4 v[F4];
                #pragma unroll
                for (int j = 0; j < F4; j++) v[j] = __ldg(h4 + node * (DIN/4) + base + j);
                accv(v, sn);
            }
            int e0 = node ? g_rowptr[node - 1] : 0;
            int e1 = g_rowptr[node];
            int e = e0;
            for (; e + 2 <= e1; e += 2) {
                int2 eA = __ldg(&g_edge[e]);
                int2 eB = __ldg(&g_edge[e + 1]);
                float wA = __int_as_float(eA.y), wB = __int_as_float(eB.y);
                float4 vA[F4], vB[F4];
                #pragma unroll
                for (int j = 0; j < F4; j++) vA[j] = __ldg(h4 + eA.x * (DIN/4) + base + j);
                #pragma unroll
                for (int j = 0; j < F4; j++) vB[j] = __ldg(h4 + eB.x * (DIN/4) + base + j);
                accv(vA, wA); accv(vB, wB);
                wsum += wA + wB;
            }
            if (e < e1) {
                int2 ev = __ldg(&g_edge[e]);
                float w = __int_as_float(ev.y);
                float4 v[F4];
                #pragma unroll
                for (int j = 0; j < F4; j++) v[j] = __ldg(h4 + ev.x * (DIN/4) + base + j);
                accv(v, w);
                wsum += w;
            }
            if (MODE_IN == 0) {
                #pragma unroll
                for (int j = 0; j < F4; j++) {
                    a[j][0] = rs[j][0]*a[j][0] + rf[j][0]*wsum;
                    a[j][1] = rs[j][1]*a[j][1] + rf[j][1]*wsum;
                    a[j][2] = rs[j][2]*a[j][2] + rf[j][2]*wsum;
                    a[j][3] = rs[j][3]*a[j][3] + rf[j][3]*wsum;
                }
            }
        }
        #pragma unroll
        for (int j = 0; j < F4; j++)
            ((float4*)sH)[local * (DIN / 4) + base + j] =
                make_float4(a[j][0], a[j][1], a[j][2], a[j][3]);
    }
    __syncthreads();

    // ---- matmul phase ----
    int cg = t % CG, rg = t / CG;
    float acc[RPT][4];
    #pragma unroll
    for (int r = 0; r < RPT; r++) { acc[r][0]=0.f; acc[r][1]=0.f; acc[r][2]=0.f; acc[r][3]=0.f; }
    const float* sHr = sH + rg * RPT * DIN;
    #pragma unroll 8
    for (int k = 0; k < DIN; k++) {
        float4 wv = *(const float4*)(sW + k * DOUT + cg * 4);
        #pragma unroll
        for (int r = 0; r < RPT; r++) {
            float hv = sHr[r * DIN + k];
            acc[r][0] += hv * wv.x; acc[r][1] += hv * wv.y;
            acc[r][2] += hv * wv.z; acc[r][3] += hv * wv.w;
        }
    }
    float b0 = bias[cg*4+0], b1 = bias[cg*4+1], b2 = bias[cg*4+2], b3 = bias[cg*4+3];
    float ls0=0.f, ls1=0.f, ls2=0.f, ls3=0.f, lq0=0.f, lq1=0.f, lq2=0.f, lq3=0.f;
    float p0=0.f, p1=0.f, p2=0.f, p3=0.f;
    int curg = -1;
    #pragma unroll
    for (int r = 0; r < RPT; r++) {
        int node = node0 + rg * RPT + r;
        if (node < NN) {
            float v0 = acc[r][0] + b0, v1 = acc[r][1] + b1;
            float v2 = acc[r][2] + b2, v3 = acc[r][3] + b3;
            if (RELU_OUT) {
                v0 = fmaxf(v0, 0.f); v1 = fmaxf(v1, 0.f);
                v2 = fmaxf(v2, 0.f); v3 = fmaxf(v3, 0.f);
            }
            if (OUT_MODE == 0) {
                ((float4*)out)[node * CG + cg] = make_float4(v0, v1, v2, v3);
            } else {
                int bg = batch[node];
                if (bg != curg) {
                    if (curg >= 0) {
                        atomicAdd(&g_pooled[curg*FMAX + cg*4+0], p0);
                        atomicAdd(&g_pooled[curg*FMAX + cg*4+1], p1);
                        atomicAdd(&g_pooled[curg*FMAX + cg*4+2], p2);
                        atomicAdd(&g_pooled[curg*FMAX + cg*4+3], p3);
                    }
                    curg = bg; p0 = v0; p1 = v1; p2 = v2; p3 = v3;
                } else {
                    p0 += v0; p1 += v1; p2 += v2; p3 += v3;
                }
            }
            ls0 += v0; lq0 += v0*v0; ls1 += v1; lq1 += v1*v1;
            ls2 += v2; lq2 += v2*v2; ls3 += v3; lq3 += v3*v3;
        }
    }
    if (OUT_MODE == 2 && curg >= 0) {
        atomicAdd(&g_pooled[curg*FMAX + cg*4+0], p0);
        atomicAdd(&g_pooled[curg*FMAX + cg*4+1], p1);
        atomicAdd(&g_pooled[curg*FMAX + cg*4+2], p2);
        atomicAdd(&g_pooled[curg*FMAX + cg*4+3], p3);
    }
    atomicAdd(&s_sum[cg*4+0], ls0); atomicAdd(&s_sq[cg*4+0], lq0);
    atomicAdd(&s_sum[cg*4+1], ls1); atomicAdd(&s_sq[cg*4+1], lq1);
    atomicAdd(&s_sum[cg*4+2], ls2); atomicAdd(&s_sq[cg*4+2], lq2);
    atomicAdd(&s_sum[cg*4+3], ls3); atomicAdd(&s_sq[cg*4+3], lq3);
    __syncthreads();
    for (int i = t; i < DOUT; i += 512) {
        atomicAdd(&g_sum[stat_out + i], (double)s_sum[i]);
        atomicAdd(&g_sq[stat_out + i],  (double)s_sq[i]);
    }
}

// ---------------- final MLP (applies BN5 to raw pooled sums) ----------------
// self-clean: zeroes its g_pooled row + g_gcnt after reading; block 0 zeroes stats384.
__global__ void mlp_kernel(const float* __restrict__ g5, const float* __restrict__ bt5,
                           const float* __restrict__ fc1_w, const float* __restrict__ fc1_b,
                           const float* __restrict__ fc2_w, const float* __restrict__ fc2_b,
                           float* __restrict__ out) {
    int g = blockIdx.x;
    int t = threadIdx.x;  // 64
    __shared__ float sp[FMAX];
    float cnt = (float)g_gcnt[g];
    for (int i = t; i < FMAX; i += 64) {
        double mu  = g_sum[512 + i] / (double)NN;
        double var = g_sq[512 + i] / (double)NN - mu * mu;
        if (var < 0.0) var = 0.0;
        double sc = (double)g5[i] * rsqrt(var + 1e-5);
        float f = (float)((double)bt5[i] - mu * sc);
        sp[i] = fmaxf((float)sc * g_pooled[g * FMAX + i] + f * cnt, 0.0f);
    }
    __syncthreads();
    // self-clean (all reads of g_pooled row / g_gcnt[g] are done)
    for (int i = t; i < FMAX; i += 64) g_pooled[g * FMAX + i] = 0.0f;
    if (t == 0) g_gcnt[g] = 0;
    if (g == 0) {
        for (int i = t; i < 128; i += 64) { g_sum[384 + i] = 0.0; g_sq[384 + i] = 0.0; }
    }
    float acc = fc1_b[t];
    #pragma unroll 4
    for (int k = 0; k < FMAX; k++) acc += sp[k] * fc1_w[k * 64 + t];
    acc = fmaxf(acc, 0.0f);
    float v = acc * fc2_w[t];
    #pragma unroll
    for (int off = 16; off > 0; off >>= 1) v += __shfl_down_sync(0xffffffffu, v, off);
    __shared__ float red[2];
    if ((t & 31) == 0) red[t >> 5] = v;
    __syncthreads();
    if (t == 0) out[g] = red[0] + red[1] + fc2_b[0];
}

// ---------------- launch ----------------
extern "C" void kernel_launch(void* const* d_in, const int* in_sizes, int n_in,
                              void* d_out, int out_size) {
    const float* x     = (const float*)d_in[0];
    const int*   ei    = (const int*)d_in[1];
    const float* ew    = (const float*)d_in[2];
    const int*   batch = (const int*)d_in[3];
    const float *W1 = (const float*)d_in[4],  *b1 = (const float*)d_in[5],
                *g1 = (const float*)d_in[6],  *bt1 = (const float*)d_in[7];
    const float *W2 = (const float*)d_in[8],  *b2 = (const float*)d_in[9],
                *g2 = (const float*)d_in[10], *bt2 = (const float*)d_in[11];
    const float *W3 = (const float*)d_in[12], *b3 = (const float*)d_in[13],
                *g3 = (const float*)d_in[14], *bt3 = (const float*)d_in[15];
    const float *W4 = (const float*)d_in[16], *b4 = (const float*)d_in[17],
                *g4 = (const float*)d_in[18], *bt4 = (const float*)d_in[19];
    const float *W5 = (const float*)d_in[20], *b5 = (const float*)d_in[21],
                *g5 = (const float*)d_in[22], *bt5 = (const float*)d_in[23];
    const float* fc1_w = (const float*)d_in[24];
    const float* fc1_b = (const float*)d_in[25];
    const float* fc2_w = (const float*)d_in[26];
    const float* fc2_b = (const float*)d_in[27];
    float* out = (float*)d_out;

    float *bufA, *bufB, *bufM;
    cudaGetSymbolAddress((void**)&bufA, g_bufA);
    cudaGetSymbolAddress((void**)&bufB, g_bufB);
    cudaGetSymbolAddress((void**)&bufM, g_m);

    // opt-in smem for the L5 fused kernel
    cudaFuncSetAttribute(
        (const void*)fused_layer_kernel<64, 128, 1, false, 64, 8, 2, 256>,
        cudaFuncAttributeMaxDynamicSharedMemorySize, 49152);

    const int TB = 256;
    count_mm_kernel<<<NC_BLOCKS + MM_BLOCKS, 256>>>(ei, ew, x, W1, bufM);
    scan_kernel<<<NB_SCAN, 1024>>>(batch);
    scatter_kernel<<<(EE + TB - 1) / TB, TB>>>(ei, ew);

    auto smem = [](int din, int dout, int tile) {
        return (din * dout + tile * din) * 4;
    };

    // L1 aggregate: m -> h1 (fp32) in bufA   (also zeroes stats512 region)
    aggregate_post_kernel<16><<<(NN * 4 + 255) / 256, 256>>>(bufM, b1, bufA, 0);

    // L2 (16->32): h1 -> h2 in bufB
    fused_layer_kernel<16, 32, 0, true, 128, 4, 0, -1>
        <<<(NN + 127) / 128, 512, smem(16, 32, 128)>>>(
        bufA, W2, b2, bufB, g1, bt1, nullptr, 0, 128);
    // L3 (32->64): h2 -> h3 in bufA   (zeroes stats0)
    fused_layer_kernel<32, 64, 0, true, 128, 4, 0, 0>
        <<<(NN + 127) / 128, 512, smem(32, 64, 128)>>>(
        bufB, W3, b3, bufA, g2, bt2, nullptr, 128, 256);
    // L4 (64->64): h3 -> c4 in bufB (no relu-out)   (zeroes stats128)
    fused_layer_kernel<64, 64, 0, false, 64, 8, 0, 128>
        <<<(NN + 63) / 64, 512, smem(64, 64, 64)>>>(
        bufA, W4, b4, bufB, g3, bt3, nullptr, 256, 384);
    // L5 (64->128): gather relu(bn(c4)); pool raw c5 per graph   (zeroes stats256)
    fused_layer_kernel<64, 128, 1, false, 64, 8, 2, 256>
        <<<(NN + 63) / 64, 512, smem(64, 128, 64)>>>(
        bufB, W5, b5, nullptr, g4, bt4, batch, 384, 512);

    // MLP head (applies BN5 affine to pooled sums; self-cleans pooled/gcnt/stats384)
    mlp_kernel<<<GG, 64>>>(g5, bt5, fc1_w, fc1_b, fc2_w, fc2_b, out);
}

// round 13
// speedup vs baseline: 1.1017x; 1.0226x over previous
#include <cuda_runtime.h>
#include <cuda_fp16.h>

#define NN 50000
#define EE 800000
#define GG 256
#define FMAX 128
#define NB_SCAN 49      // ceil(50000/1024)
#define NC_BLOCKS 3125  // ceil(EE/256)
#define MM_BLOCKS 592

// stat offsets: L1=0(16) L2=128(32) L3=256(64) L4=384(64) L5=512(128)
// Self-cleaning invariant: every global below is returned to ZERO by the
// kernel that consumes it, so no init pass is needed across graph replays.
__device__ unsigned long long g_pack[NN];   // count<<42 | weightsum_fx32
__device__ float  g_dis[NN];
__device__ int    g_rowptr[NN + 1];
__device__ int    g_blocksum[64];
__device__ int    g_gcnt[GG];
__device__ int    g_bar1;
__device__ int2   g_edge[EE];          // {src, float_bits(norm_w)}
__device__ float  g_bufA[NN * 64];     // h1(16) / h3(64)
__device__ float  g_bufB[NN * 64];     // h2(32) / c4(64)
__device__ float  g_m[NN * 16];        // L1 matmul out
__device__ double g_sum[640];
__device__ double g_sq[640];
__device__ float  g_pooled[GG * FMAX]; // raw per-graph sums of c5

// fused: blocks [0,NC) count edges; blocks [NC,NC+MM) do m = x @ W1 (independent)
__global__ __launch_bounds__(256)
void count_mm_kernel(const int* __restrict__ ei, const float* __restrict__ ew,
                     const float* __restrict__ x, const float* __restrict__ W1,
                     float* __restrict__ out) {
    if (blockIdx.x < NC_BLOCKS) {
        int e = blockIdx.x * 256 + threadIdx.x;
        if (e < EE) {
            int c = ei[EE + e];
            unsigned long long p = (1ULL << 42) |
                (unsigned long long)(ew[e] * 4294967296.0f);
            atomicAdd(&g_pack[c], p);
        }
        return;
    }
    int lane = threadIdx.x & 31;
    int bid = blockIdx.x - NC_BLOCKS;
    int gwarp = (bid * 256 + threadIdx.x) >> 5;
    const int nwarps = MM_BLOCKS * 8;
    float w[4][16];
    #pragma unroll
    for (int j = 0; j < 4; j++) {
        #pragma unroll
        for (int c = 0; c < 16; c += 4) {
            float4 v = __ldg((const float4*)(W1 + (lane * 4 + j) * 16 + c));
            w[j][c] = v.x; w[j][c+1] = v.y; w[j][c+2] = v.z; w[j][c+3] = v.w;
        }
    }
    for (int node = gwarp; node < NN; node += nwarps) {
        float4 xv = __ldg((const float4*)(x + node * 128 + lane * 4));
        float acc[16];
        #pragma unroll
        for (int c = 0; c < 16; c++)
            acc[c] = xv.x * w[0][c] + xv.y * w[1][c] + xv.z * w[2][c] + xv.w * w[3][c];
        #pragma unroll
        for (int r = 0; r < 4; r++) {
            const int off  = 16 >> r;
            const int nrem = 8 >> r;
            bool hi = (lane & off) != 0;
            #pragma unroll
            for (int j = 0; j < nrem; j++) {
                float send = hi ? acc[j] : acc[j + nrem];
                float keep = hi ? acc[j + nrem] : acc[j];
                acc[j] = keep + __shfl_xor_sync(0xffffffffu, send, off);
            }
        }
        acc[0] += __shfl_xor_sync(0xffffffffu, acc[0], 1);
        if (!(lane & 1)) out[node * 16 + (lane >> 1)] = acc[0];
    }
}

// merged scan: dis + gcnt + local scan -> [gbar] -> global rowptr starts
// self-clean: zeroes g_pack after reading it.
__global__ __launch_bounds__(1024)
void scan_kernel(const int* __restrict__ batch) {
    __shared__ int s[1024];
    __shared__ int soff;
    int t = threadIdx.x;
    int i = blockIdx.x * 1024 + t;
    unsigned long long p = (i < NN) ? g_pack[i] : 0ULL;
    int v = (int)(p >> 42);
    s[t] = v;
    if (i < NN) {
        g_pack[i] = 0ULL;   // self-clean for next replay
        double wfx = (double)(p & ((1ULL << 42) - 1ULL)) * 2.3283064365386963e-10;
        g_dis[i] = rsqrtf((float)(1.0 + wfx));
        atomicAdd(&g_gcnt[batch[i]], 1);
    }
    __syncthreads();
    #pragma unroll
    for (int off = 1; off < 1024; off <<= 1) {
        int x = (t >= off) ? s[t - off] : 0;
        __syncthreads();
        s[t] += x;
        __syncthreads();
    }
    int local_excl = s[t] - v;
    if (t == 1023) g_blocksum[blockIdx.x] = s[1023];
    __syncthreads();
    if (t == 0) {
        __threadfence();
        atomicAdd(&g_bar1, 1);
        while (atomicAdd(&g_bar1, 0) < NB_SCAN) __nanosleep(32);
        int off = 0;
        for (int b = 0; b < blockIdx.x; b++) off += g_blocksum[b];
        soff = off;
    }
    __syncthreads();
    if (i < NN) g_rowptr[i] = soff + local_excl;
}

// scatter; rowptr[c] doubles as fill cursor. self-clean: resets g_bar1.
__global__ void scatter_kernel(const int* __restrict__ ei, const float* __restrict__ ew) {
    if (blockIdx.x == 0 && threadIdx.x == 0) g_bar1 = 0;  // scan fully done
    int e = blockIdx.x * blockDim.x + threadIdx.x;
    if (e < EE) {
        int r = ei[e];
        int c = ei[EE + e];
        int pos = atomicAdd(&g_rowptr[c], 1);
        float w = g_dis[r] * ew[e] * g_dis[c];
        g_edge[pos] = make_int2(r, __float_as_int(w));
    }
}

// ---------------- L1 aggregate + bias + relu + stats ----------------
// 4-edge unroll (grid shape unchanged). self-clean: block 0 zeroes stats512.
template <int DOUT>
__global__ __launch_bounds__(256)
void aggregate_post_kernel(const float* __restrict__ m, const float* __restrict__ b,
                           float* __restrict__ out, int stat_off) {
    constexpr int NT  = DOUT / 4;
    constexpr int NPB = 256 / NT;
    __shared__ float s_sum[DOUT], s_sq[DOUT];
    int tid = threadIdx.x;
    if (blockIdx.x == 0) {
        for (int i = tid; i < 128; i += 256) { g_sum[512 + i] = 0.0; g_sq[512 + i] = 0.0; }
    }
    for (int i = tid; i < DOUT; i += 256) { s_sum[i] = 0.f; s_sq[i] = 0.f; }
    __syncthreads();
    int lane = tid % NT;
    int node = blockIdx.x * NPB + tid / NT;
    const float4* m4 = (const float4*)m;
    if (node < NN) {
        float dn = g_dis[node];
        float sn = dn * dn;
        float a0 = b[lane*4+0], a1 = b[lane*4+1], a2 = b[lane*4+2], a3 = b[lane*4+3];
        float4 mv = __ldg(m4 + node * NT + lane);
        a0 += sn * mv.x; a1 += sn * mv.y; a2 += sn * mv.z; a3 += sn * mv.w;
        int e0 = node ? g_rowptr[node - 1] : 0;
        int e1 = g_rowptr[node];
        int e = e0;
        for (; e + 4 <= e1; e += 4) {
            int2 eA = __ldg(&g_edge[e]);
            int2 eB = __ldg(&g_edge[e + 1]);
            int2 eC = __ldg(&g_edge[e + 2]);
            int2 eD = __ldg(&g_edge[e + 3]);
            float wA = __int_as_float(eA.y), wB = __int_as_float(eB.y);
            float wC = __int_as_float(eC.y), wD = __int_as_float(eD.y);
            float4 vA = __ldg(m4 + eA.x * NT + lane);
            float4 vB = __ldg(m4 + eB.x * NT + lane);
            float4 vC = __ldg(m4 + eC.x * NT + lane);
            float4 vD = __ldg(m4 + eD.x * NT + lane);
            a0 += wA*vA.x + wB*vB.x + wC*vC.x + wD*vD.x;
            a1 += wA*vA.y + wB*vB.y + wC*vC.y + wD*vD.y;
            a2 += wA*vA.z + wB*vB.z + wC*vC.z + wD*vD.z;
            a3 += wA*vA.w + wB*vB.w + wC*vC.w + wD*vD.w;
        }
        for (; e < e1; e++) {
            int2 ev = __ldg(&g_edge[e]);
            float w = __int_as_float(ev.y);
            float4 v = __ldg(m4 + ev.x * NT + lane);
            a0 += w * v.x; a1 += w * v.y; a2 += w * v.z; a3 += w * v.w;
        }
        a0 = fmaxf(a0, 0.f); a1 = fmaxf(a1, 0.f);
        a2 = fmaxf(a2, 0.f); a3 = fmaxf(a3, 0.f);
        ((float4*)out)[node * NT + lane] = make_float4(a0, a1, a2, a3);
        atomicAdd(&s_sum[lane*4+0], a0); atomicAdd(&s_sq[lane*4+0], a0*a0);
        atomicAdd(&s_sum[lane*4+1], a1); atomicAdd(&s_sq[lane*4+1], a1*a1);
        atomicAdd(&s_sum[lane*4+2], a2); atomicAdd(&s_sq[lane*4+2], a2*a2);
        atomicAdd(&s_sum[lane*4+3], a3); atomicAdd(&s_sq[lane*4+3], a3*a3);
    }
    __syncthreads();
    for (int i = tid; i < DOUT; i += 256) {
        atomicAdd(&g_sum[stat_off + i], (double)s_sum[i]);
        atomicAdd(&g_sq[stat_off + i],  (double)s_sq[i]);
    }
}

// ---------------- fused: gather(BN-in) -> matmul -> bias(+relu) + stats [+pool] ----------------
// MODE_IN 0: bn folded out of loop; 1: relu(bn) per element.
// OUT_MODE 0: write float4 rows; 2: no output buffer, pool raw values per graph.
// STAT_ZERO >= 0: block 0 zeroes stats region [STAT_ZERO, STAT_ZERO+128).
// Gather loop software-pipelines the edge-index loads one pair ahead.
template <int DIN, int DOUT, int MODE_IN, bool RELU_OUT, int TILE, int TPN, int OUT_MODE,
          int STAT_ZERO>
__global__ __launch_bounds__(512)
void fused_layer_kernel(const float* __restrict__ h, const float* __restrict__ W,
                        const float* __restrict__ bias, float* __restrict__ out,
                        const float* __restrict__ gamma, const float* __restrict__ beta,
                        const int* __restrict__ batch,
                        int stat_in, int stat_out) {
    static_assert(TILE * TPN == 512, "gather uses all threads");
    constexpr int CG  = DOUT / 4;
    constexpr int RG  = 512 / CG;
    constexpr int RPT = TILE / RG;
    constexpr int F4  = DIN / 4 / TPN;
    extern __shared__ float smem[];
    float* sW = smem;
    float* sH = smem + DIN * DOUT;
    __shared__ float sS[DIN], sF[DIN];
    __shared__ float s_sum[DOUT], s_sq[DOUT];
    int t = threadIdx.x;
    if (STAT_ZERO >= 0 && blockIdx.x == 0) {
        for (int i = t; i < 128; i += 512) {
            g_sum[STAT_ZERO + i] = 0.0; g_sq[STAT_ZERO + i] = 0.0;
        }
    }
    if (t < DIN) {
        double mu  = g_sum[stat_in + t] / (double)NN;
        double var = g_sq[stat_in + t] / (double)NN - mu * mu;
        if (var < 0.0) var = 0.0;
        double sc = (double)gamma[t] * rsqrt(var + 1e-5);
        sS[t] = (float)sc;
        sF[t] = (float)((double)beta[t] - mu * sc);
    }
    for (int i = t; i < DOUT; i += 512) { s_sum[i] = 0.f; s_sq[i] = 0.f; }
    for (int i = t; i < DIN * DOUT / 4; i += 512)
        ((float4*)sW)[i] = ((const float4*)W)[i];
    __syncthreads();

    int node0 = blockIdx.x * TILE;
    // ---- gather phase ----
    {
        int local = t / TPN;
        int sub   = t % TPN;
        int base  = sub * F4;
        int node  = node0 + local;
        float a[F4][4];
        #pragma unroll
        for (int j = 0; j < F4; j++) { a[j][0]=0.f; a[j][1]=0.f; a[j][2]=0.f; a[j][3]=0.f; }
        if (node < NN) {
            const float4* h4 = (const float4*)h;
            float rs[F4][4], rf[F4][4];
            #pragma unroll
            for (int j = 0; j < F4; j++) {
                int c = (base + j) * 4;
                rs[j][0]=sS[c]; rs[j][1]=sS[c+1]; rs[j][2]=sS[c+2]; rs[j][3]=sS[c+3];
                rf[j][0]=sF[c]; rf[j][1]=sF[c+1]; rf[j][2]=sF[c+2]; rf[j][3]=sF[c+3];
            }
            auto accv = [&](const float4* v, float w) {
                #pragma unroll
                for (int j = 0; j < F4; j++) {
                    if (MODE_IN == 1) {
                        a[j][0] += w * fmaxf(rs[j][0]*v[j].x + rf[j][0], 0.f);
                        a[j][1] += w * fmaxf(rs[j][1]*v[j].y + rf[j][1], 0.f);
                        a[j][2] += w * fmaxf(rs[j][2]*v[j].z + rf[j][2], 0.f);
                        a[j][3] += w * fmaxf(rs[j][3]*v[j].w + rf[j][3], 0.f);
                    } else {
                        a[j][0] += w*v[j].x; a[j][1] += w*v[j].y;
                        a[j][2] += w*v[j].z; a[j][3] += w*v[j].w;
                    }
                }
            };
            float dn = g_dis[node];
            float sn = dn * dn;
            float wsum = sn;
            {
                float4 v[F4];
                #pragma unroll
                for (int j = 0; j < F4; j++) v[j] = __ldg(h4 + node * (DIN/4) + base + j);
                accv(v, sn);
            }
            int e0 = node ? g_rowptr[node - 1] : 0;
            int e1 = g_rowptr[node];
            int e = e0;
            // software-pipelined 2-edge loop: edge indices prefetched one pair ahead
            int2 eA, eB;
            if (e + 2 <= e1) { eA = __ldg(&g_edge[e]); eB = __ldg(&g_edge[e + 1]); }
            for (; e + 2 <= e1; ) {
                int2 nA, nB;
                if (e + 4 <= e1) { nA = __ldg(&g_edge[e + 2]); nB = __ldg(&g_edge[e + 3]); }
                float wA = __int_as_float(eA.y), wB = __int_as_float(eB.y);
                float4 vA[F4], vB[F4];
                #pragma unroll
                for (int j = 0; j < F4; j++) vA[j] = __ldg(h4 + eA.x * (DIN/4) + base + j);
                #pragma unroll
                for (int j = 0; j < F4; j++) vB[j] = __ldg(h4 + eB.x * (DIN/4) + base + j);
                accv(vA, wA); accv(vB, wB);
                wsum += wA + wB;
                eA = nA; eB = nB;
                e += 2;
            }
            if (e < e1) {
                int2 ev = __ldg(&g_edge[e]);
                float w = __int_as_float(ev.y);
                float4 v[F4];
                #pragma unroll
                for (int j = 0; j < F4; j++) v[j] = __ldg(h4 + ev.x * (DIN/4) + base + j);
                accv(v, w);
                wsum += w;
            }
            if (MODE_IN == 0) {
                #pragma unroll
                for (int j = 0; j < F4; j++) {
                    a[j][0] = rs[j][0]*a[j][0] + rf[j][0]*wsum;
                    a[j][1] = rs[j][1]*a[j][1] + rf[j][1]*wsum;
                    a[j][2] = rs[j][2]*a[j][2] + rf[j][2]*wsum;
                    a[j][3] = rs[j][3]*a[j][3] + rf[j][3]*wsum;
                }
            }
        }
        #pragma unroll
        for (int j = 0; j < F4; j++)
            ((float4*)sH)[local * (DIN / 4) + base + j] =
                make_float4(a[j][0], a[j][1], a[j][2], a[j][3]);
    }
    __syncthreads();

    // ---- matmul phase ----
    int cg = t % CG, rg = t / CG;
    float acc[RPT][4];
    #pragma unroll
    for (int r = 0; r < RPT; r++) { acc[r][0]=0.f; acc[r][1]=0.f; acc[r][2]=0.f; acc[r][3]=0.f; }
    const float* sHr = sH + rg * RPT * DIN;
    #pragma unroll 8
    for (int k = 0; k < DIN; k++) {
        float4 wv = *(const float4*)(sW + k * DOUT + cg * 4);
        #pragma unroll
        for (int r = 0; r < RPT; r++) {
            float hv = sHr[r * DIN + k];
            acc[r][0] += hv * wv.x; acc[r][1] += hv * wv.y;
            acc[r][2] += hv * wv.z; acc[r][3] += hv * wv.w;
        }
    }
    float b0 = bias[cg*4+0], b1 = bias[cg*4+1], b2 = bias[cg*4+2], b3 = bias[cg*4+3];
    float ls0=0.f, ls1=0.f, ls2=0.f, ls3=0.f, lq0=0.f, lq1=0.f, lq2=0.f, lq3=0.f;
    float p0=0.f, p1=0.f, p2=0.f, p3=0.f;
    int curg = -1;
    #pragma unroll
    for (int r = 0; r < RPT; r++) {
        int node = node0 + rg * RPT + r;
        if (node < NN) {
            float v0 = acc[r][0] + b0, v1 = acc[r][1] + b1;
            float v2 = acc[r][2] + b2, v3 = acc[r][3] + b3;
            if (RELU_OUT) {
                v0 = fmaxf(v0, 0.f); v1 = fmaxf(v1, 0.f);
                v2 = fmaxf(v2, 0.f); v3 = fmaxf(v3, 0.f);
            }
            if (OUT_MODE == 0) {
                ((float4*)out)[node * CG + cg] = make_float4(v0, v1, v2, v3);
            } else {
                int bg = batch[node];
                if (bg != curg) {
                    if (curg >= 0) {
                        atomicAdd(&g_pooled[curg*FMAX + cg*4+0], p0);
                        atomicAdd(&g_pooled[curg*FMAX + cg*4+1], p1);
                        atomicAdd(&g_pooled[curg*FMAX + cg*4+2], p2);
                        atomicAdd(&g_pooled[curg*FMAX + cg*4+3], p3);
                    }
                    curg = bg; p0 = v0; p1 = v1; p2 = v2; p3 = v3;
                } else {
                    p0 += v0; p1 += v1; p2 += v2; p3 += v3;
                }
            }
            ls0 += v0; lq0 += v0*v0; ls1 += v1; lq1 += v1*v1;
            ls2 += v2; lq2 += v2*v2; ls3 += v3; lq3 += v3*v3;
        }
    }
    if (OUT_MODE == 2 && curg >= 0) {
        atomicAdd(&g_pooled[curg*FMAX + cg*4+0], p0);
        atomicAdd(&g_pooled[curg*FMAX + cg*4+1], p1);
        atomicAdd(&g_pooled[curg*FMAX + cg*4+2], p2);
        atomicAdd(&g_pooled[curg*FMAX + cg*4+3], p3);
    }
    atomicAdd(&s_sum[cg*4+0], ls0); atomicAdd(&s_sq[cg*4+0], lq0);
    atomicAdd(&s_sum[cg*4+1], ls1); atomicAdd(&s_sq[cg*4+1], lq1);
    atomicAdd(&s_sum[cg*4+2], ls2); atomicAdd(&s_sq[cg*4+2], lq2);
    atomicAdd(&s_sum[cg*4+3], ls3); atomicAdd(&s_sq[cg*4+3], lq3);
    __syncthreads();
    for (int i = t; i < DOUT; i += 512) {
        atomicAdd(&g_sum[stat_out + i], (double)s_sum[i]);
        atomicAdd(&g_sq[stat_out + i],  (double)s_sq[i]);
    }
}

// ---------------- final MLP (applies BN5 to raw pooled sums) ----------------
// self-clean: zeroes its g_pooled row + g_gcnt after reading; block 0 zeroes stats384.
__global__ void mlp_kernel(const float* __restrict__ g5, const float* __restrict__ bt5,
                           const float* __restrict__ fc1_w, const float* __restrict__ fc1_b,
                           const float* __restrict__ fc2_w, const float* __restrict__ fc2_b,
                           float* __restrict__ out) {
    int g = blockIdx.x;
    int t = threadIdx.x;  // 64
    __shared__ float sp[FMAX];
    float cnt = (float)g_gcnt[g];
    for (int i = t; i < FMAX; i += 64) {
        double mu  = g_sum[512 + i] / (double)NN;
        double var = g_sq[512 + i] / (double)NN - mu * mu;
        if (var < 0.0) var = 0.0;
        double sc = (double)g5[i] * rsqrt(var + 1e-5);
        float f = (float)((double)bt5[i] - mu * sc);
        sp[i] = fmaxf((float)sc * g_pooled[g * FMAX + i] + f * cnt, 0.0f);
    }
    __syncthreads();
    // self-clean (all reads of g_pooled row / g_gcnt[g] are done)
    for (int i = t; i < FMAX; i += 64) g_pooled[g * FMAX + i] = 0.0f;
    if (t == 0) g_gcnt[g] = 0;
    if (g == 0) {
        for (int i = t; i < 128; i += 64) { g_sum[384 + i] = 0.0; g_sq[384 + i] = 0.0; }
    }
    float acc = fc1_b[t];
    #pragma unroll 4
    for (int k = 0; k < FMAX; k++) acc += sp[k] * fc1_w[k * 64 + t];
    acc = fmaxf(acc, 0.0f);
    float v = acc * fc2_w[t];
    #pragma unroll
    for (int off = 16; off > 0; off >>= 1) v += __shfl_down_sync(0xffffffffu, v, off);
    __shared__ float red[2];
    if ((t & 31) == 0) red[t >> 5] = v;
    __syncthreads();
    if (t == 0) out[g] = red[0] + red[1] + fc2_b[0];
}

// ---------------- launch ----------------
extern "C" void kernel_launch(void* const* d_in, const int* in_sizes, int n_in,
                              void* d_out, int out_size) {
    const float* x     = (const float*)d_in[0];
    const int*   ei    = (const int*)d_in[1];
    const float* ew    = (const float*)d_in[2];
    const int*   batch = (const int*)d_in[3];
    const float *W1 = (const float*)d_in[4],  *b1 = (const float*)d_in[5],
                *g1 = (const float*)d_in[6],  *bt1 = (const float*)d_in[7];
    const float *W2 = (const float*)d_in[8],  *b2 = (const float*)d_in[9],
                *g2 = (const float*)d_in[10], *bt2 = (const float*)d_in[11];
    const float *W3 = (const float*)d_in[12], *b3 = (const float*)d_in[13],
                *g3 = (const float*)d_in[14], *bt3 = (const float*)d_in[15];
    const float *W4 = (const float*)d_in[16], *b4 = (const float*)d_in[17],
                *g4 = (const float*)d_in[18], *bt4 = (const float*)d_in[19];
    const float *W5 = (const float*)d_in[20], *b5 = (const float*)d_in[21],
                *g5 = (const float*)d_in[22], *bt5 = (const float*)d_in[23];
    const float* fc1_w = (const float*)d_in[24];
    const float* fc1_b = (const float*)d_in[25];
    const float* fc2_w = (const float*)d_in[26];
    const float* fc2_b = (const float*)d_in[27];
    float* out = (float*)d_out;

    float *bufA, *bufB, *bufM;
    cudaGetSymbolAddress((void**)&bufA, g_bufA);
    cudaGetSymbolAddress((void**)&bufB, g_bufB);
    cudaGetSymbolAddress((void**)&bufM, g_m);

    // opt-in smem for the L5 fused kernel
    cudaFuncSetAttribute(
        (const void*)fused_layer_kernel<64, 128, 1, false, 64, 8, 2, 256>,
        cudaFuncAttributeMaxDynamicSharedMemorySize, 49152);

    const int TB = 256;
    count_mm_kernel<<<NC_BLOCKS + MM_BLOCKS, 256>>>(ei, ew, x, W1, bufM);
    scan_kernel<<<NB_SCAN, 1024>>>(batch);
    scatter_kernel<<<(EE + TB - 1) / TB, TB>>>(ei, ew);

    auto smem = [](int din, int dout, int tile) {
        return (din * dout + tile * din) * 4;
    };

    // L1 aggregate: m -> h1 (fp32) in bufA   (also zeroes stats512 region)
    aggregate_post_kernel<16><<<(NN * 4 + 255) / 256, 256>>>(bufM, b1, bufA, 0);

    // L2 (16->32): h1 -> h2 in bufB
    fused_layer_kernel<16, 32, 0, true, 128, 4, 0, -1>
        <<<(NN + 127) / 128, 512, smem(16, 32, 128)>>>(
        bufA, W2, b2, bufB, g1, bt1, nullptr, 0, 128);
    // L3 (32->64): h2 -> h3 in bufA   (zeroes stats0)
    fused_layer_kernel<32, 64, 0, true, 128, 4, 0, 0>
        <<<(NN + 127) / 128, 512, smem(32, 64, 128)>>>(
        bufB, W3, b3, bufA, g2, bt2, nullptr, 128, 256);
    // L4 (64->64): h3 -> c4 in bufB (no relu-out)   (zeroes stats128)
    fused_layer_kernel<64, 64, 0, false, 64, 8, 0, 128>
        <<<(NN + 63) / 64, 512, smem(64, 64, 64)>>>(
        bufA, W4, b4, bufB, g3, bt3, nullptr, 256, 384);
    // L5 (64->128): gather relu(bn(c4)); pool raw c5 per graph   (zeroes stats256)
    fused_layer_kernel<64, 128, 1, false, 64, 8, 2, 256>
        <<<(NN + 63) / 64, 512, smem(64, 128, 64)>>>(
        bufB, W5, b5, nullptr, g4, bt4, batch, 384, 512);

    // MLP head (applies BN5 affine to pooled sums; self-cleans pooled/gcnt/stats384)
    mlp_kernel<<<GG, 64>>>(g5, bt5, fc1_w, fc1_b, fc2_w, fc2_b, out);
}